// round 1
// baseline (speedup 1.0000x reference)
#include <cuda_runtime.h>
#include <cstdint>

// DropEmbedding:
//   out[s,b,:] = ( rowscale(X[s,b]) * W[X[s,b],:] ) .* lockmask(b,:)
// rowscale(t) = (u_embed[t] < 0.9f) ? 1/0.9f : 0
// lockmask(b,d) = (u_lock[b,d] < 0.35f) ? 1/0.35f : 0
//
// Shapes: X[S=2048,B=8] int32, W[V=50257,D=1024] f32,
//         u_embed[V,1] f32, u_lock[1,B,D] f32, out[S,B,D] f32.
// HBM-bound: ~64 MiB gather-read + ~64 MiB write.

static constexpr int SEQ   = 2048;
static constexpr int BATCH = 8;
static constexpr int NINP  = 1024;

static constexpr float KEEP_E = 0.9f;    // 1 - 0.1
static constexpr float KEEP_I = 0.35f;   // 1 - 0.65

__global__ __launch_bounds__(256, 8)
void drop_embedding_kernel(const int* __restrict__ X,
                           const float* __restrict__ W,
                           const float* __restrict__ u_embed,
                           const float* __restrict__ u_lock,
                           float* __restrict__ out)
{
    // One CTA per output row (s,b). 256 threads x float4 = 1024 floats.
    const int r   = blockIdx.x;          // r = s*BATCH + b
    const int b   = r & (BATCH - 1);     // BATCH = 8
    const int tok = __ldg(&X[r]);        // warp-uniform load

    // Row-wise embedding-dropout scale (warp-uniform).
    const float ue = __ldg(&u_embed[tok]);
    const float rowscale = (ue < KEEP_E) ? (1.0f / KEEP_E) : 0.0f;

    const int d = threadIdx.x << 2;      // float4 lane

    const float4 w = *reinterpret_cast<const float4*>(W + (size_t)tok * NINP + d);
    const float4 u = *reinterpret_cast<const float4*>(u_lock + b * NINP + d);

    const float inv_ki = 1.0f / KEEP_I;
    float4 o;
    // Match reference op order: (rowscale * W) * lockmask
    o.x = (rowscale * w.x) * ((u.x < KEEP_I) ? inv_ki : 0.0f);
    o.y = (rowscale * w.y) * ((u.y < KEEP_I) ? inv_ki : 0.0f);
    o.z = (rowscale * w.z) * ((u.z < KEEP_I) ? inv_ki : 0.0f);
    o.w = (rowscale * w.w) * ((u.w < KEEP_I) ? inv_ki : 0.0f);

    *reinterpret_cast<float4*>(out + (size_t)r * NINP + d) = o;
}

extern "C" void kernel_launch(void* const* d_in, const int* in_sizes, int n_in,
                              void* d_out, int out_size)
{
    const int*   X  = (const int*)  d_in[0];   // [SEQ, BATCH] int32
    const float* W  = (const float*)d_in[1];   // [VOCAB, NINP]
    const float* ue = (const float*)d_in[2];   // [VOCAB, 1]
    const float* ul = (const float*)d_in[3];   // [1, BATCH, NINP]
    float* out = (float*)d_out;                // [SEQ, BATCH, NINP]

    const int rows = SEQ * BATCH;              // 16384 CTAs
    drop_embedding_kernel<<<rows, 256>>>(X, W, ue, ul, out);
}

// round 2
// speedup vs baseline: 1.3179x; 1.3179x over previous
#include <cuda_runtime.h>
#include <cstdint>

// DropEmbedding:
//   out[s,b,:] = ( rowscale(X[s,b]) * W[X[s,b],:] ) .* lockmask(b,:)
// rowscale(t)   = (u_embed[t]  < 0.9f ) ? 1/0.9f  : 0
// lockmask(b,d) = (u_lock[b,d] < 0.35f) ? 1/0.35f : 0
//
// R2: latency-bound fix — 4 rows per CTA, front-batched independent LDG.128s
// (MLP_p1 ~8/thread) + streaming stores (__stcs) so the write-once output
// doesn't evict gathered W rows from L2.

static constexpr int SEQ   = 2048;
static constexpr int BATCH = 8;
static constexpr int NINP  = 1024;
static constexpr int RPC   = 4;          // rows per CTA

static constexpr float KEEP_E = 0.9f;    // 1 - 0.1
static constexpr float KEEP_I = 0.35f;   // 1 - 0.65

__global__ __launch_bounds__(256)
void drop_embedding_kernel(const int* __restrict__ X,
                           const float* __restrict__ W,
                           const float* __restrict__ u_embed,
                           const float* __restrict__ u_lock,
                           float* __restrict__ out)
{
    const int r0 = blockIdx.x * RPC;     // first row (s*BATCH+b) of this CTA
    const int d  = threadIdx.x << 2;     // float4 lane within the 1024-dim row

    // ---- front-batch everything independent ----
    int tok[RPC];
    #pragma unroll
    for (int i = 0; i < RPC; i++)
        tok[i] = __ldg(&X[r0 + i]);                       // warp-uniform

    float4 w[RPC], u[RPC];
    #pragma unroll
    for (int i = 0; i < RPC; i++)
        w[i] = *reinterpret_cast<const float4*>(W + (size_t)tok[i] * NINP + d);
    #pragma unroll
    for (int i = 0; i < RPC; i++) {
        const int b = (r0 + i) & (BATCH - 1);
        u[i] = *reinterpret_cast<const float4*>(u_lock + b * NINP + d);
    }

    float rs[RPC];
    #pragma unroll
    for (int i = 0; i < RPC; i++) {
        const float ue = __ldg(&u_embed[tok[i]]);         // warp-uniform
        rs[i] = (ue < KEEP_E) ? (1.0f / KEEP_E) : 0.0f;
    }

    // ---- compute + streaming store ----
    const float inv_ki = 1.0f / KEEP_I;
    #pragma unroll
    for (int i = 0; i < RPC; i++) {
        float4 o;
        // Match reference op order: (rowscale * W) * lockmask
        o.x = (rs[i] * w[i].x) * ((u[i].x < KEEP_I) ? inv_ki : 0.0f);
        o.y = (rs[i] * w[i].y) * ((u[i].y < KEEP_I) ? inv_ki : 0.0f);
        o.z = (rs[i] * w[i].z) * ((u[i].z < KEEP_I) ? inv_ki : 0.0f);
        o.w = (rs[i] * w[i].w) * ((u[i].w < KEEP_I) ? inv_ki : 0.0f);
        __stcs(reinterpret_cast<float4*>(out + (size_t)(r0 + i) * NINP + d), o);
    }
}

extern "C" void kernel_launch(void* const* d_in, const int* in_sizes, int n_in,
                              void* d_out, int out_size)
{
    const int*   X  = (const int*)  d_in[0];   // [SEQ, BATCH] int32
    const float* W  = (const float*)d_in[1];   // [VOCAB, NINP]
    const float* ue = (const float*)d_in[2];   // [VOCAB, 1]
    const float* ul = (const float*)d_in[3];   // [1, BATCH, NINP]
    float* out = (float*)d_out;                // [SEQ, BATCH, NINP]

    const int rows = SEQ * BATCH;              // 16384
    drop_embedding_kernel<<<rows / RPC, 256>>>(X, W, ue, ul, out);
}

// round 4
// speedup vs baseline: 1.5670x; 1.1890x over previous
#include <cuda_runtime.h>
#include <cstdint>

// DropEmbedding:
//   out[s,b,:] = ( rowscale(X[s,b]) * W[X[s,b],:] ) .* lockmask(b,:)
// rowscale(t)   = (u_embed[t]  < 0.9f ) ? 1/0.9f  : 0
// lockmask(b,d) = (u_lock[b,d] < 0.35f) ? 1/0.35f : 0
//
// R3 (re-bench; previous attempt hit a broker/container failure, no metrics):
// same-batch row grouping — each CTA handles 8 rows with the SAME batch index
// b (consecutive s), so ONE u_lock float4 load serves all 8 rows.
// Per-thread: 8 front-batched W LDG.128 (MLP_p1~9) + 1 cached u load.
// Streaming stores for the write-once output.

static constexpr int SEQ   = 2048;
static constexpr int BATCH = 8;
static constexpr int NINP  = 1024;
static constexpr int RPC   = 8;          // rows per CTA (same b, consecutive s)

static constexpr float KEEP_E = 0.9f;    // 1 - 0.1
static constexpr float KEEP_I = 0.35f;   // 1 - 0.65

__global__ __launch_bounds__(256)
void drop_embedding_kernel(const int* __restrict__ X,
                           const float* __restrict__ W,
                           const float* __restrict__ u_embed,
                           const float* __restrict__ u_lock,
                           float* __restrict__ out)
{
    // CTA -> (b, s0): b cycles fastest so consecutive CTAs write adjacent rows.
    const int b  = blockIdx.x & (BATCH - 1);
    const int s0 = (blockIdx.x >> 3) * RPC;
    const int d  = threadIdx.x << 2;     // float4 lane within the 1024-dim row

    const int* __restrict__ xrow = X + s0 * BATCH + b;

    // ---- front-batch all independent loads ----
    int tok[RPC];
    #pragma unroll
    for (int i = 0; i < RPC; i++)
        tok[i] = __ldg(&xrow[i * BATCH]);                  // warp-uniform

    float4 w[RPC];
    #pragma unroll
    for (int i = 0; i < RPC; i++)
        w[i] = *reinterpret_cast<const float4*>(W + (size_t)tok[i] * NINP + d);

    // One lock-mask vector serves all RPC rows (same b).
    const float4 u = *reinterpret_cast<const float4*>(u_lock + b * NINP + d);

    float rs[RPC];
    #pragma unroll
    for (int i = 0; i < RPC; i++) {
        const float ue = __ldg(&u_embed[tok[i]]);          // warp-uniform
        rs[i] = (ue < KEEP_E) ? (1.0f / KEEP_E) : 0.0f;
    }

    const float inv_ki = 1.0f / KEEP_I;
    const float lm_x = (u.x < KEEP_I) ? inv_ki : 0.0f;
    const float lm_y = (u.y < KEEP_I) ? inv_ki : 0.0f;
    const float lm_z = (u.z < KEEP_I) ? inv_ki : 0.0f;
    const float lm_w = (u.w < KEEP_I) ? inv_ki : 0.0f;

    // ---- compute + streaming store ----
    #pragma unroll
    for (int i = 0; i < RPC; i++) {
        float4 o;
        // Match reference op order: (rowscale * W) * lockmask
        o.x = (rs[i] * w[i].x) * lm_x;
        o.y = (rs[i] * w[i].y) * lm_y;
        o.z = (rs[i] * w[i].z) * lm_z;
        o.w = (rs[i] * w[i].w) * lm_w;
        __stcs(reinterpret_cast<float4*>(
                   out + (size_t)((s0 + i) * BATCH + b) * NINP + d), o);
    }
}

extern "C" void kernel_launch(void* const* d_in, const int* in_sizes, int n_in,
                              void* d_out, int out_size)
{
    const int*   X  = (const int*)  d_in[0];   // [SEQ, BATCH] int32
    const float* W  = (const float*)d_in[1];   // [VOCAB, NINP]
    const float* ue = (const float*)d_in[2];   // [VOCAB, 1]
    const float* ul = (const float*)d_in[3];   // [1, BATCH, NINP]
    float* out = (float*)d_out;                // [SEQ, BATCH, NINP]

    const int rows = SEQ * BATCH;              // 16384
    drop_embedding_kernel<<<rows / RPC, 256>>>(X, W, ue, ul, out);
}